// round 11
// baseline (speedup 1.0000x reference)
#include <cuda_runtime.h>
#include <cuda_bf16.h>
#include <cstdint>

// NLTKHierarchicalSoftmax: B=4096, NHID=512, BR=32, DEPTH=3
// Round 11: R10 structure + cp.async double-buffered x staging.
//   x for superchunk sc+1 is cp.async'd while sc computes (distance 1),
//   eliminating the LDG->STS latency exposure at every superchunk boundary.
//   W register double-buffer prefetch unchanged (measured best).

#define FULL 0xffffffffu
#define NHID 512
#define BR 32
#define NB2 1024
#define BTOT 4096
#define WNODE (NHID*BR)
#define NL0 512
#define NL1 512
#define NCTA 256
#define WARPS_PER_CTA 8
// per warp: 2 buffers x 8 samples x 128 floats = 8KB; 8 warps = 64KB dynamic
#define DSMEM_BYTES (WARPS_PER_CTA * 2 * 8 * 128 * 4)

__device__ int g_off[NB2 + 1];
__device__ int g_sorted[BTOT];
__device__ float g_p[3 * BTOT];
__device__ int g_done;               // zero-init; reset by last CTA

typedef unsigned long long u64t;

__device__ __forceinline__ u64t ffma2(u64t a, u64t b, u64t c)
{
    u64t d;
    asm("fma.rn.f32x2 %0, %1, %2, %3;" : "=l"(d) : "l"(a), "l"(b), "l"(c));
    return d;
}
__device__ __forceinline__ u64t packf2(float lo, float hi)
{
    u64t d;
    asm("mov.b64 %0, {%1, %2};" : "=l"(d) : "f"(lo), "f"(hi));
    return d;
}
__device__ __forceinline__ float2 unpackf2(u64t v)
{
    float2 r;
    asm("mov.b64 {%0, %1}, %2;" : "=f"(r.x), "=f"(r.y) : "l"(v));
    return r;
}
__device__ __forceinline__ unsigned sm32(const void* p)
{
    return (unsigned)__cvta_generic_to_shared(p);
}
__device__ __forceinline__ void cp16(unsigned d, const void* s)
{
    asm volatile("cp.async.cg.shared.global [%0], [%1], 16;" :: "r"(d), "l"(s));
}
__device__ __forceinline__ void cp_commit()
{
    asm volatile("cp.async.commit_group;");
}
__device__ __forceinline__ void cp_wait1()
{
    asm volatile("cp.async.wait_group 1;" ::: "memory");
}
__device__ __forceinline__ void cp_wait0()
{
    asm volatile("cp.async.wait_group 0;" ::: "memory");
}

// ---------------- counting sort (single CTA, 1024 thr, batched loads) ---------
__global__ void __launch_bounds__(NB2) k_sort(const int* __restrict__ labels, int B)
{
    __shared__ int cnt[NB2];
    __shared__ int cur[NB2];
    __shared__ int wsum[32];
    int t = threadIdx.x;
    int lane = t & 31;
    int warp = t >> 5;

    cnt[t] = 0;
    __syncthreads();

    int l0 = (t        < B) ? __ldg(&labels[t])        : -1;
    int l1 = (t + 1024 < B) ? __ldg(&labels[t + 1024]) : -1;
    int l2 = (t + 2048 < B) ? __ldg(&labels[t + 2048]) : -1;
    int l3 = (t + 3072 < B) ? __ldg(&labels[t + 3072]) : -1;
    if (l0 >= 0) atomicAdd(&cnt[l0 >> 5], 1);
    if (l1 >= 0) atomicAdd(&cnt[l1 >> 5], 1);
    if (l2 >= 0) atomicAdd(&cnt[l2 >> 5], 1);
    if (l3 >= 0) atomicAdd(&cnt[l3 >> 5], 1);
    __syncthreads();

    int v = cnt[t];
    int inc = v;
    #pragma unroll
    for (int o = 1; o < 32; o <<= 1) {
        int u = __shfl_up_sync(FULL, inc, o);
        if (lane >= o) inc += u;
    }
    if (lane == 31) wsum[warp] = inc;
    __syncthreads();
    if (t < 32) {
        int wv = wsum[t];
        int wi = wv;
        #pragma unroll
        for (int o = 1; o < 32; o <<= 1) {
            int u = __shfl_up_sync(FULL, wi, o);
            if (t >= o) wi += u;
        }
        wsum[t] = wi - wv;
    }
    __syncthreads();

    int excl = wsum[warp] + inc - v;
    g_off[t] = excl;
    cur[t] = excl;
    if (t == NB2 - 1) g_off[NB2] = excl + v;
    __syncthreads();

    if (l0 >= 0) g_sorted[atomicAdd(&cur[l0 >> 5], 1)] = t;
    if (l1 >= 0) g_sorted[atomicAdd(&cur[l1 >> 5], 1)] = t + 1024;
    if (l2 >= 0) g_sorted[atomicAdd(&cur[l2 >> 5], 1)] = t + 2048;
    if (l3 >= 0) g_sorted[atomicAdd(&cur[l3 >> 5], 1)] = t + 3072;
}

// ---------------- pipelined run processor: W regs + cp.async x ----------------
// xbuf: per-warp double buffer, xbuf[buf][s][h] (2 x 8 x 128 floats)
template<int TS>
__device__ __forceinline__ void stage_x(
    float (*xbuf)[8][128], int buf, const float* __restrict__ x,
    const int* bs, int sc, int lane)
{
    #pragma unroll
    for (int s = 0; s < TS; s++)
        cp16(sm32(&xbuf[buf][s][lane * 4]),
             x + (size_t)bs[s] * NHID + sc * 128 + lane * 4);
    cp_commit();
}

template<int TS>
__device__ __forceinline__ void process_run(
    const float* __restrict__ x, const float* __restrict__ Wn,
    const int* bs, unsigned msk, const int* step,
    int lane, float (*xbuf)[8][128], float* __restrict__ pout)
{
    u64t acc2[TS];
    #pragma unroll
    for (int s = 0; s < TS; s++) acc2[s] = 0ull;

    // prologue: x superchunk 0 in flight, W subchunk 0 in regs
    stage_x<TS>(xbuf, 0, x, bs, 0, lane);

    float wr[2][16];
    #pragma unroll
    for (int k = 0; k < 16; k++)
        wr[0][k] = __ldg(Wn + k * BR + lane);

    #pragma unroll 1
    for (int sc = 0; sc < 4; sc++) {            // 4 superchunks of 128 h
        if (sc < 3) {
            stage_x<TS>(xbuf, (sc + 1) & 1, x, bs, sc + 1, lane);
            cp_wait1();                          // sc's buffer is complete
        } else {
            cp_wait0();
        }
        __syncwarp();
        const float (*xsm)[128] = xbuf[sc & 1];

        #pragma unroll
        for (int sub = 0; sub < 8; sub++) {     // 8 subchunks of 16 h
            const int curb = sub & 1;
            const int subg = sc * 8 + sub;
            if (subg + 1 < 32) {                // prefetch next subchunk W
                int h0 = (subg + 1) * 16;
                #pragma unroll
                for (int k = 0; k < 16; k++)
                    wr[curb ^ 1][k] = __ldg(Wn + (h0 + k) * BR + lane);
            }
            u64t wp[8];
            #pragma unroll
            for (int k = 0; k < 8; k++)
                wp[k] = packf2(wr[curb][2 * k], wr[curb][2 * k + 1]);

            #pragma unroll
            for (int q = 0; q < 4; q++) {
                #pragma unroll
                for (int s = 0; s < TS; s++) {  // independent acc chains
                    ulonglong2 xq =
                        *(const ulonglong2*)&xsm[s][sub * 16 + q * 4];
                    acc2[s] = ffma2(xq.x, wp[2 * q], acc2[s]);
                    acc2[s] = ffma2(xq.y, wp[2 * q + 1], acc2[s]);
                }
            }
        }
        __syncwarp();                            // buffer reuse fence
    }

    // per-sample warp softmax over 32 columns (lane = column)
    #pragma unroll
    for (int s = 0; s < TS; s++) {
        if (msk & (1u << s)) {
            float2 h = unpackf2(acc2[s]);
            float acc = h.x + h.y;
            float m = acc;
            #pragma unroll
            for (int o = 16; o > 0; o >>= 1)
                m = fmaxf(m, __shfl_xor_sync(FULL, m, o));
            float e = __expf(acc - m);
            float sum = e;
            #pragma unroll
            for (int o = 16; o > 0; o >>= 1)
                sum += __shfl_xor_sync(FULL, sum, o);
            float est = __shfl_sync(FULL, e, step[s]);
            if (lane == 0) pout[bs[s]] = est / sum;
        }
    }
}

// ---------------- work kernel --------------------------------------------------
__global__ void __launch_bounds__(32 * WARPS_PER_CTA, 2) k_work(
    const float* __restrict__ x, const int* __restrict__ labels,
    const float* __restrict__ W, float* __restrict__ out, int B)
{
    extern __shared__ __align__(16) float dyn_smem[];
    __shared__ int s_last;

    const int tid = threadIdx.x;
    const int lane = tid & 31;
    const int wid = tid >> 5;
    int gw = blockIdx.x * WARPS_PER_CTA + wid;
    float (*xbuf)[8][128] =
        reinterpret_cast<float (*)[8][128]>(dyn_smem + wid * 2 * 8 * 128);

    if (gw < NL0) {
        // level 0: node 0, natural order (no sort dependency)
        int s0 = gw * 8;
        int bs[8], step[8];
        unsigned msk = 0;
        #pragma unroll
        for (int s = 0; s < 8; s++) {
            int b = min(s0 + s, B - 1);
            bs[s] = b;
            step[s] = (__ldg(&labels[b]) >> 10) & 31;
            if (s0 + s < B) msk |= 1u << s;
        }
        process_run<8>(x, W, bs, msk, step, lane, xbuf, g_p);
    } else if (gw < NL0 + NL1) {
        // level 1: tiles of 8 consecutive sorted samples; node = 1 + (lab>>10)
        int s0 = (gw - NL0) * 8;
        int bs[8], step[8], node[8];
        #pragma unroll
        for (int s = 0; s < 8; s++) {
            int idx = min(s0 + s, B - 1);
            int b = __ldg(&g_sorted[idx]);
            bs[s] = b;
            int lab = __ldg(&labels[b]);
            node[s] = 1 + (lab >> 10);
            step[s] = (lab >> 5) & 31;
        }
        unsigned valid = (s0 + 8 <= B) ? 0xffu : ((1u << (B - s0)) - 1u);
        unsigned rem = valid;
        while (rem) {
            int src = __ffs(rem) - 1;
            int n = node[src];
            unsigned msk = 0;
            #pragma unroll
            for (int s = 0; s < 8; s++)
                if (node[s] == n) msk |= 1u << s;
            msk &= valid;
            process_run<8>(x, W + (size_t)n * WNODE, bs, msk, step, lane, xbuf,
                           g_p + BTOT);
            rem &= ~msk;
        }
    } else if (gw < NL0 + NL1 + NB2) {
        // level 2: one warp per bucket (node = 33 + bucket)
        int w = gw - NL0 - NL1;
        int beg = __ldg(&g_off[w]);
        int end = __ldg(&g_off[w + 1]);
        const float* Wn = W + (size_t)(33 + w) * WNODE;

        int t = beg;
        while (end - t >= 5) {
            int G = min(8, end - t);
            int bs[8], step[8];
            #pragma unroll
            for (int s = 0; s < 8; s++) {
                int idx = t + ((s < G) ? s : (G - 1));
                int b = __ldg(&g_sorted[idx]);
                bs[s] = b;
                step[s] = __ldg(&labels[b]) & 31;
            }
            unsigned msk = (G >= 8) ? 0xffu : ((1u << G) - 1u);
            process_run<8>(x, Wn, bs, msk, step, lane, xbuf, g_p + 2 * BTOT);
            t += G;
        }
        if (t < end) {
            int G = end - t;
            int bs[4], step[4];
            #pragma unroll
            for (int s = 0; s < 4; s++) {
                int idx = t + ((s < G) ? s : (G - 1));
                int b = __ldg(&g_sorted[idx]);
                bs[s] = b;
                step[s] = __ldg(&labels[b]) & 31;
            }
            process_run<4>(x, Wn, bs, (1u << G) - 1u, step, lane, xbuf,
                           g_p + 2 * BTOT);
        }
    }

    // completion: last CTA computes the 3-factor product
    __syncthreads();
    __threadfence();
    if (tid == 0) {
        int old = atomicAdd(&g_done, 1);
        s_last = (old == NCTA - 1) ? 1 : 0;
    }
    __syncthreads();
    if (s_last) {
        __threadfence();
        for (int i = tid; i < B; i += 256)
            out[i] = g_p[i] * g_p[BTOT + i] * g_p[2 * BTOT + i];
        if (tid == 0) g_done = 0;   // reset for next graph replay
    }
}

extern "C" void kernel_launch(void* const* d_in, const int* in_sizes, int n_in,
                              void* d_out, int out_size)
{
    const float* x      = (const float*)d_in[0];
    const int*   labels = (const int*)d_in[1];
    const float* W      = (const float*)d_in[2];
    float* out = (float*)d_out;

    int B = in_sizes[1];  // 4096

    k_sort<<<1, NB2>>>(labels, B);

    cudaFuncSetAttribute(k_work, cudaFuncAttributeMaxDynamicSharedMemorySize,
                         DSMEM_BYTES);
    k_work<<<NCTA, 256, DSMEM_BYTES>>>(x, labels, W, out, B);
}